// round 4
// baseline (speedup 1.0000x reference)
#include <cuda_runtime.h>
#include <cstddef>

#define BS 8
#define CLS 4
#define CCH 256
#define HW 16384
#define LL 19
#define TK 256
#define MH 64
#define MW 64

typedef unsigned long long u64;

// Scratch (device globals: allocation is forbidden)
__device__ float g_M[TK * CCH];       // M[k][c] = sum_t W2[t][k] * W1[t][c]
__device__ float g_W3T[TK * CCH];     // W3T[k][c] = W3[c][k]
__device__ float g_U[BS][LL][TK];     // (tok @ M) / 16
__device__ float g_t3[BS][LL][CCH];   // tok @ W3^T + b3
__device__ float g_a[BS][HW][20];     // softmaxed attn weights (19 used, padded)

// ---------------- f32x2 packed helpers (sm_103a) ----------------
__device__ __forceinline__ u64 pk2(float lo, float hi) {
    u64 r;
    asm("mov.b64 %0, {%1, %2};" : "=l"(r) : "f"(lo), "f"(hi));
    return r;
}
__device__ __forceinline__ void upk2(float& lo, float& hi, u64 v) {
    asm("mov.b64 {%0, %1}, %2;" : "=f"(lo), "=f"(hi) : "l"(v));
}
__device__ __forceinline__ u64 fma2(u64 a, u64 b, u64 c) {
    u64 d;
    asm("fma.rn.f32x2 %0, %1, %2, %3;" : "=l"(d) : "l"(a), "l"(b), "l"(c));
    return d;
}

// ---------------------------------------------------------------------------
// wprep: M[k][c] = sum_t W2[t][k]*W1[t][c]  and  W3T[k][c] = W3[c][k]
// grid = 64 (k-chunks of 4), 256 threads (c)
// ---------------------------------------------------------------------------
__global__ void __launch_bounds__(256) wprep_kernel(const float* __restrict__ W1,
                                                    const float* __restrict__ W2,
                                                    const float* __restrict__ W3) {
    int k0 = blockIdx.x * 4;
    int c = threadIdx.x;
    __shared__ float w2s[256][4];
    __shared__ float w3s[256][5];  // padded vs bank conflicts on transpose read
    for (int i = threadIdx.x; i < 1024; i += 256) {
        int r = i >> 2, j = i & 3;
        w2s[r][j] = W2[r * TK + k0 + j];
        w3s[r][j] = W3[r * TK + k0 + j];
    }
    __syncthreads();

    float acc[4] = {0.f, 0.f, 0.f, 0.f};
#pragma unroll 8
    for (int t = 0; t < 256; t++) {
        float w1 = W1[t * CCH + c];
#pragma unroll
        for (int j = 0; j < 4; j++) acc[j] = fmaf(w2s[t][j], w1, acc[j]);
    }
#pragma unroll
    for (int j = 0; j < 4; j++) {
        g_M[(k0 + j) * CCH + c] = acc[j];
        g_W3T[(k0 + j) * CCH + c] = w3s[c][j];
    }
}

// ---------------------------------------------------------------------------
// tokprep: U[b][l][c] = (1/16) sum_k tok[b][l][k]*M[k][c]
//          t3[b][l][c] = sum_k tok[b][l][k]*W3T[k][c] + b3[c]
// grid = (BS, 10): y/5 = phase (0:U, 1:t3), y%5 = l-group of 4 (last has 3)
// ---------------------------------------------------------------------------
__global__ void __launch_bounds__(256) tokprep_kernel(const float* __restrict__ token_s,
                                                      const float* __restrict__ b3) {
    int b = blockIdx.x;
    int y = blockIdx.y;
    int phase = y / 5;
    int l0 = (y % 5) * 4;
    int lcnt = (l0 + 4 <= LL) ? 4 : (LL - l0);
    int c = threadIdx.x;

    __shared__ float tok[4][256];
    for (int i = threadIdx.x; i < 4 * 256; i += 256) {
        int l = i >> 8, k = i & 255;
        tok[l][k] = (l < lcnt) ? token_s[(b * LL + l0 + l) * TK + k] : 0.f;
    }
    __syncthreads();

    const float* Mp = phase ? g_W3T : g_M;
    float acc[4] = {0.f, 0.f, 0.f, 0.f};
#pragma unroll 8
    for (int k = 0; k < 256; k++) {
        float m = Mp[k * CCH + c];
#pragma unroll
        for (int l = 0; l < 4; l++) acc[l] = fmaf(tok[l][k], m, acc[l]);
    }
    if (phase == 0) {
        for (int l = 0; l < lcnt; l++) g_U[b][l0 + l][c] = acc[l] * 0.0625f;
    } else {
        float bias = b3[c];
        for (int l = 0; l < lcnt; l++) g_t3[b][l0 + l][c] = acc[l] + bias;
    }
}

// ---------------------------------------------------------------------------
// attn3: f32x2 lanes = (even channel, odd channel). 2 batches per block.
// Groups g: 0:{0,2} 1:{4,6} (sources 0..3), 2:{1,3} 3:{5,7} (sources 4..7).
// logits[l] = sum_c fea_c[b,c,n] * U[b][l][c]  (U carries the 1/16),
// softmax over l, zero where raw logit == 0, store g_a.
// grid = (4, HW/128), 128 threads (1 px each). dyn smem = 2*19*256*4 = 38912 B.
// ---------------------------------------------------------------------------
extern __shared__ float Us[];  // [2][19][256] floats = [2][19][128] c-pairs

__global__ void __launch_bounds__(128) attn3_kernel(const float* __restrict__ mask,
                                                    const float* __restrict__ fea) {
    int g = blockIdx.x;
    int b0 = (g & 1) * 4 + (g >> 1);  // 0,4,1,5
    int b1 = b0 + 2;
    int p = g >> 1;                   // source parity
    int tid = threadIdx.x;

    for (int idx = tid; idx < 2 * LL * TK; idx += 128) {
        int bi = idx / (LL * TK);
        int rem = idx - bi * (LL * TK);
        Us[idx] = (&g_U[bi ? b1 : b0][0][0])[rem];
    }
    __syncthreads();

    int n = blockIdx.y * 128 + tid;
    int mi = blockIdx.y >> 1;  // row i = blockIdx.y, mi = i>>1
    int mj = tid >> 1;

    u64 mp[2][4];
#pragma unroll
    for (int bi = 0; bi < 2; bi++) {
        int b = bi ? b1 : b0;
#pragma unroll
        for (int s = 0; s < 4; s++) {
            float m = 0.25f * mask[((b * CLS + s) * MH + mi) * MW + mj];
            mp[bi][s] = pk2(m, m);
        }
    }

    const float* fp0 = fea + (size_t)(4 * p + 0) * CCH * HW + n;
    const float* fp1 = fea + (size_t)(4 * p + 1) * CCH * HW + n;
    const float* fp2 = fea + (size_t)(4 * p + 2) * CCH * HW + n;
    const float* fp3 = fea + (size_t)(4 * p + 3) * CCH * HW + n;

    u64 acc0[LL], acc1[LL];
#pragma unroll
    for (int l = 0; l < LL; l++) { acc0[l] = 0ULL; acc1[l] = 0ULL; }

    const u64* U0 = (const u64*)Us;             // [19][128]
    const u64* U1 = (const u64*)(Us + LL * TK);

#pragma unroll 2
    for (int cp = 0; cp < 128; cp++) {
        size_t offA = (size_t)(2 * cp) * HW;
        size_t offB = offA + HW;
        u64 fs0 = pk2(__ldg(fp0 + offA), __ldg(fp0 + offB));
        u64 fs1 = pk2(__ldg(fp1 + offA), __ldg(fp1 + offB));
        u64 fs2 = pk2(__ldg(fp2 + offA), __ldg(fp2 + offB));
        u64 fs3 = pk2(__ldg(fp3 + offA), __ldg(fp3 + offB));

        u64 cb0 = fma2(mp[0][3], fs3,
                  fma2(mp[0][2], fs2,
                  fma2(mp[0][1], fs1,
                  fma2(mp[0][0], fs0, 0ULL))));
        u64 cb1 = fma2(mp[1][3], fs3,
                  fma2(mp[1][2], fs2,
                  fma2(mp[1][1], fs1,
                  fma2(mp[1][0], fs0, 0ULL))));
#pragma unroll
        for (int l = 0; l < LL; l++) {
            acc0[l] = fma2(cb0, U0[l * 128 + cp], acc0[l]);
            acc1[l] = fma2(cb1, U1[l * 128 + cp], acc1[l]);
        }
    }

    // epilogue: softmax per (batch, pixel), zero where raw logit == 0
#pragma unroll
    for (int bi = 0; bi < 2; bi++) {
        int b = bi ? b1 : b0;
        float lg[LL];
#pragma unroll
        for (int l = 0; l < LL; l++) {
            float lo, hi;
            upk2(lo, hi, bi ? acc1[l] : acc0[l]);
            lg[l] = lo + hi;
        }
        float mx = lg[0];
#pragma unroll
        for (int l = 1; l < LL; l++) mx = fmaxf(mx, lg[l]);
        float e[LL], sum = 0.f;
#pragma unroll
        for (int l = 0; l < LL; l++) { e[l] = __expf(lg[l] - mx); sum += e[l]; }
        float inv = 1.f / sum;
        float outv[20];
#pragma unroll
        for (int l = 0; l < LL; l++) outv[l] = (lg[l] != 0.f) ? e[l] * inv : 0.f;
        outv[19] = 0.f;
        float4* dst = (float4*)g_a[b][n];
#pragma unroll
        for (int q = 0; q < 5; q++) dst[q] = ((float4*)outv)[q];
    }
}

// ---------------------------------------------------------------------------
// out2: out[b,c,n] = fea[b,c,n] + sum_l a[b,n,l] * t3[b,l,c]
// f32x2 lanes = (even channel, odd channel); t3 pair via broadcast LDS.64,
// a duplicated-packed per pixel in registers. 2 px/thread.
// grid = (BS, HW/512, 2 c-tiles of 128), 256 threads.
// ---------------------------------------------------------------------------
__global__ void __launch_bounds__(256) out2_kernel(const float* __restrict__ fea,
                                                   float* __restrict__ out) {
    int b = blockIdx.x;
    int c0 = blockIdx.z * 128;

    __shared__ float t3s[LL][128];
    for (int idx = threadIdx.x; idx < LL * 128; idx += 256) {
        int l = idx >> 7, c = idx & 127;
        t3s[l][c] = g_t3[b][l][c0 + c];
    }
    __syncthreads();

    int n1 = blockIdx.y * 512 + threadIdx.x;
    int n2 = n1 + 256;

    float a1[20], a2[20];
#pragma unroll
    for (int q = 0; q < 5; q++) {
        ((float4*)a1)[q] = ((const float4*)g_a[b][n1])[q];
        ((float4*)a2)[q] = ((const float4*)g_a[b][n2])[q];
    }
    u64 a1d[LL], a2d[LL];
#pragma unroll
    for (int l = 0; l < LL; l++) { a1d[l] = pk2(a1[l], a1[l]); a2d[l] = pk2(a2[l], a2[l]); }

    const float* fp = fea + (size_t)b * CCH * HW;
    float* op = out + (size_t)b * CCH * HW;
    const u64* t3p = (const u64*)&t3s[0][0];  // [19][64] c-pairs

#pragma unroll 2
    for (int cp = 0; cp < 64; cp++) {
        u64 v1 = 0ULL, v2 = 0ULL;
#pragma unroll
        for (int l = 0; l < LL; l++) {
            u64 t = t3p[l * 64 + cp];
            v1 = fma2(a1d[l], t, v1);
            v2 = fma2(a2d[l], t, v2);
        }
        float v1lo, v1hi, v2lo, v2hi;
        upk2(v1lo, v1hi, v1);
        upk2(v2lo, v2hi, v2);
        size_t offA = (size_t)(c0 + 2 * cp) * HW;
        size_t offB = offA + HW;
        op[offA + n1] = fp[offA + n1] + v1lo;
        op[offB + n1] = fp[offB + n1] + v1hi;
        op[offA + n2] = fp[offA + n2] + v2lo;
        op[offB + n2] = fp[offB + n2] + v2hi;
    }
}

extern "C" void kernel_launch(void* const* d_in, const int* in_sizes, int n_in,
                              void* d_out, int out_size) {
    const float* mask    = (const float*)d_in[0];
    const float* fea     = (const float*)d_in[1];
    const float* token_s = (const float*)d_in[2];
    const float* W1      = (const float*)d_in[3];
    const float* W2      = (const float*)d_in[4];
    const float* W3      = (const float*)d_in[5];
    const float* b3      = (const float*)d_in[6];
    float* out = (float*)d_out;

    wprep_kernel<<<64, 256>>>(W1, W2, W3);
    tokprep_kernel<<<dim3(BS, 10), 256>>>(token_s, b3);
    attn3_kernel<<<dim3(4, HW / 128), 128, 2 * LL * TK * sizeof(float)>>>(mask, fea);
    out2_kernel<<<dim3(BS, HW / 512, 2), 256>>>(fea, out);
}

// round 5
// speedup vs baseline: 1.2656x; 1.2656x over previous
#include <cuda_runtime.h>
#include <cstddef>

#define BS 8
#define CLS 4
#define CCH 256
#define HW 16384
#define LL 19
#define TK 256
#define MH 64
#define MW 64

typedef unsigned long long u64;

// Scratch (device globals: allocation is forbidden)
__device__ float g_M[TK * CCH];       // M[k][c] = sum_t W2[t][k] * W1[t][c]
__device__ float g_W3T[TK * CCH];     // W3T[k][c] = W3[c][k]
__device__ float g_U[BS][LL][TK];     // (tok @ M) / 16
__device__ float g_t3[BS][LL][CCH];   // tok @ W3^T + b3
__device__ float g_a[BS][HW][20];     // softmaxed attn weights (19 used, padded)

// ---------------- f32x2 packed helpers (sm_103a) ----------------
__device__ __forceinline__ u64 pk2(float lo, float hi) {
    u64 r;
    asm("mov.b64 %0, {%1, %2};" : "=l"(r) : "f"(lo), "f"(hi));
    return r;
}
__device__ __forceinline__ void upk2(float& lo, float& hi, u64 v) {
    asm("mov.b64 {%0, %1}, %2;" : "=f"(lo), "=f"(hi) : "l"(v));
}
__device__ __forceinline__ u64 fma2(u64 a, u64 b, u64 c) {
    u64 d;
    asm("fma.rn.f32x2 %0, %1, %2, %3;" : "=l"(d) : "l"(a), "l"(b), "l"(c));
    return d;
}

// ---------------------------------------------------------------------------
// wprep: M[k][c] = sum_t W2[t][k]*W1[t][c]  and  W3T[k][c] = W3[c][k]
// ---------------------------------------------------------------------------
__global__ void __launch_bounds__(256) wprep_kernel(const float* __restrict__ W1,
                                                    const float* __restrict__ W2,
                                                    const float* __restrict__ W3) {
    int k0 = blockIdx.x * 4;
    int c = threadIdx.x;
    __shared__ float w2s[256][4];
    __shared__ float w3s[256][5];
    for (int i = threadIdx.x; i < 1024; i += 256) {
        int r = i >> 2, j = i & 3;
        w2s[r][j] = W2[r * TK + k0 + j];
        w3s[r][j] = W3[r * TK + k0 + j];
    }
    __syncthreads();

    float acc[4] = {0.f, 0.f, 0.f, 0.f};
#pragma unroll 8
    for (int t = 0; t < 256; t++) {
        float w1 = W1[t * CCH + c];
#pragma unroll
        for (int j = 0; j < 4; j++) acc[j] = fmaf(w2s[t][j], w1, acc[j]);
    }
#pragma unroll
    for (int j = 0; j < 4; j++) {
        g_M[(k0 + j) * CCH + c] = acc[j];
        g_W3T[(k0 + j) * CCH + c] = w3s[c][j];
    }
}

// ---------------------------------------------------------------------------
// tokprep: U[b][l][c] = (1/16) sum_k tok[b][l][k]*M[k][c]
//          t3[b][l][c] = sum_k tok[b][l][k]*W3T[k][c] + b3[c]
// ---------------------------------------------------------------------------
__global__ void __launch_bounds__(256) tokprep_kernel(const float* __restrict__ token_s,
                                                      const float* __restrict__ b3) {
    int b = blockIdx.x;
    int y = blockIdx.y;
    int phase = y / 5;
    int l0 = (y % 5) * 4;
    int lcnt = (l0 + 4 <= LL) ? 4 : (LL - l0);
    int c = threadIdx.x;

    __shared__ float tok[4][256];
    for (int i = threadIdx.x; i < 4 * 256; i += 256) {
        int l = i >> 8, k = i & 255;
        tok[l][k] = (l < lcnt) ? token_s[(b * LL + l0 + l) * TK + k] : 0.f;
    }
    __syncthreads();

    const float* Mp = phase ? g_W3T : g_M;
    float acc[4] = {0.f, 0.f, 0.f, 0.f};
#pragma unroll 8
    for (int k = 0; k < 256; k++) {
        float m = Mp[k * CCH + c];
#pragma unroll
        for (int l = 0; l < 4; l++) acc[l] = fmaf(tok[l][k], m, acc[l]);
    }
    if (phase == 0) {
        for (int l = 0; l < lcnt; l++) g_U[b][l0 + l][c] = acc[l] * 0.0625f;
    } else {
        float bias = b3[c];
        for (int l = 0; l < lcnt; l++) g_t3[b][l0 + l][c] = acc[l] + bias;
    }
}

// ---------------------------------------------------------------------------
// attn4: smem-tiled. Block = (group g of 2 batches, image row of 128 px).
// Phase A per 32-ch chunk: X[b][ch][pp] = sum_s m[b][s][pp] * fea[src][ch][px-pair]
// Phase B: per-warp (batch, 5 l) x per-thread (2 pp) register tile:
//   logits += X * Udup  (Udup = broadcast LDS.64, amortized over 64 pp)
// Epilogue: softmax over 19 l per (b,px), zero where logit==0, store g_a.
// grid = (4, 128), 256 threads. static smem = 47104 B.
// ---------------------------------------------------------------------------
__global__ void __launch_bounds__(256) attn4_kernel(const float* __restrict__ mask,
                                                    const float* __restrict__ fea) {
    __shared__ u64 Xs[2][32][64];     // 32 KB ; aliased as Asm at the end
    __shared__ u64 Udup[2][20][32];   // 10 KB
    __shared__ u64 Mdup[2][4][64];    // 4 KB

    int g = blockIdx.x;
    int row = blockIdx.y;
    int b0 = (g & 1) * 4 + (g >> 1);  // {0,2},{4,6},{1,3},{5,7}
    int b1 = b0 + 2;
    int p = g >> 1;                    // source parity: 0 -> fea 0..3, 1 -> 4..7
    int tid = threadIdx.x;
    int w = tid >> 5, lane = tid & 31;

    // stage mask row (2 batches x 4 classes x 64), duplicated pairs, *0.25
    int mi = row >> 1;
    for (int idx = tid; idx < 2 * 4 * 64; idx += 256) {
        int bi = idx >> 8, rem = idx & 255;
        int s = rem >> 6, mj = rem & 63;
        int b = bi ? b1 : b0;
        float m = 0.25f * mask[((b * CLS + s) * MH + mi) * MW + mj];
        Mdup[bi][s][mj] = pk2(m, m);
    }

    int bsel = w & 1;
    int l0 = (w >> 1) * 5;  // 0,5,10,15 (last group: l=19 is a zero pad)

    const float* fbase[4];
#pragma unroll
    for (int s = 0; s < 4; s++)
        fbase[s] = fea + (size_t)(4 * p + s) * CCH * HW + row * 128;

    u64 acc[5][2];
#pragma unroll
    for (int i = 0; i < 5; i++) { acc[i][0] = 0ULL; acc[i][1] = 0ULL; }

    __syncthreads();  // Mdup ready

    for (int kc = 0; kc < 8; kc++) {
        // build Udup for this chunk (row l=19 zero-padded)
        for (int idx = tid; idx < 2 * 20 * 32; idx += 256) {
            int bi = idx / 640;
            int rem = idx - bi * 640;
            int l = rem >> 5, k = rem & 31;
            float u = (l < LL) ? g_U[bi ? b1 : b0][l][kc * 32 + k] : 0.f;
            Udup[bi][l][k] = pk2(u, u);
        }
        // build X: 2048 (ch,pp) jobs, 8 per thread
#pragma unroll
        for (int r = 0; r < 8; r++) {
            int j = r * 256 + tid;
            int ch = j >> 6, pp = j & 63;
            size_t off = (size_t)(kc * 32 + ch) * HW + 2 * pp;
            u64 f0 = *(const u64*)(fbase[0] + off);
            u64 f1 = *(const u64*)(fbase[1] + off);
            u64 f2 = *(const u64*)(fbase[2] + off);
            u64 f3 = *(const u64*)(fbase[3] + off);
            u64 cb0 = fma2(Mdup[0][3][pp], f3,
                      fma2(Mdup[0][2][pp], f2,
                      fma2(Mdup[0][1][pp], f1,
                      fma2(Mdup[0][0][pp], f0, 0ULL))));
            u64 cb1 = fma2(Mdup[1][3][pp], f3,
                      fma2(Mdup[1][2][pp], f2,
                      fma2(Mdup[1][1][pp], f1,
                      fma2(Mdup[1][0][pp], f0, 0ULL))));
            Xs[0][ch][pp] = cb0;
            Xs[1][ch][pp] = cb1;
        }
        __syncthreads();  // X + Udup ready

        const u64* Xb = &Xs[bsel][0][0];
#pragma unroll 8
        for (int k = 0; k < 32; k++) {
            u64 x0 = Xb[k * 64 + lane];
            u64 x1 = Xb[k * 64 + lane + 32];
#pragma unroll
            for (int i = 0; i < 5; i++) {
                u64 u = Udup[bsel][l0 + i][k];
                acc[i][0] = fma2(x0, u, acc[i][0]);
                acc[i][1] = fma2(x1, u, acc[i][1]);
            }
        }
        __syncthreads();  // done reading before next chunk overwrites
    }

    // exchange logits via smem (alias Xs): Asm u64 view [2][20][64 pp]
    u64* Asm = &Xs[0][0][0];
#pragma unroll
    for (int i = 0; i < 5; i++) {
        Asm[(bsel * 20 + l0 + i) * 64 + lane] = acc[i][0];
        Asm[(bsel * 20 + l0 + i) * 64 + lane + 32] = acc[i][1];
    }
    __syncthreads();

    // softmax: thread = (bq, px)
    const float* Af = (const float*)Asm;  // [2][20][128]
    int bq = tid >> 7, px = tid & 127;
    int b = bq ? b1 : b0;
    float lg[LL];
#pragma unroll
    for (int l = 0; l < LL; l++) lg[l] = Af[(bq * 20 + l) * 128 + px];
    float mx = lg[0];
#pragma unroll
    for (int l = 1; l < LL; l++) mx = fmaxf(mx, lg[l]);
    float e[LL], sum = 0.f;
#pragma unroll
    for (int l = 0; l < LL; l++) { e[l] = __expf(lg[l] - mx); sum += e[l]; }
    float inv = 1.f / sum;
    float outv[20];
#pragma unroll
    for (int l = 0; l < LL; l++) outv[l] = (lg[l] != 0.f) ? e[l] * inv : 0.f;
    outv[19] = 0.f;
    float4* dst = (float4*)g_a[b][row * 128 + px];
#pragma unroll
    for (int q = 0; q < 5; q++) dst[q] = ((float4*)outv)[q];
}

// ---------------------------------------------------------------------------
// out3: out[b,c,n] = fea[b,c,n] + sum_l a[b,n,l] * t3[b,l,c]
// f32x2 lanes = (pixel n1, pixel n2): a packed in 19 regs, t3 via broadcast
// LDS.64 from duplicated smem. Channel loop unrolled for MLP.
// grid = (BS, 32, 2 c-halves), 256 threads, 2 px/thread.
// ---------------------------------------------------------------------------
__global__ void __launch_bounds__(256) out3_kernel(const float* __restrict__ fea,
                                                   float* __restrict__ out) {
    int b = blockIdx.x;
    int c0 = blockIdx.z * 128;

    __shared__ u64 t3d[LL][128];  // duplicated pairs, 19456 B
    for (int idx = threadIdx.x; idx < LL * 128; idx += 256) {
        int l = idx >> 7, c = idx & 127;
        float v = g_t3[b][l][c0 + c];
        t3d[l][c] = pk2(v, v);
    }
    __syncthreads();

    int n1 = blockIdx.y * 512 + threadIdx.x;
    int n2 = n1 + 256;

    u64 ap[LL];
    {
        const float4* pa1 = (const float4*)g_a[b][n1];
        const float4* pa2 = (const float4*)g_a[b][n2];
#pragma unroll
        for (int q = 0; q < 5; q++) {
            float4 qa = pa1[q];
            float4 qb = pa2[q];
            int base = q * 4;
            if (base + 0 < LL) ap[base + 0] = pk2(qa.x, qb.x);
            if (base + 1 < LL) ap[base + 1] = pk2(qa.y, qb.y);
            if (base + 2 < LL) ap[base + 2] = pk2(qa.z, qb.z);
            if (base + 3 < LL) ap[base + 3] = pk2(qa.w, qb.w);
        }
    }

    const float* fp = fea + (size_t)b * CCH * HW + (size_t)c0 * HW;
    float* op = out + (size_t)b * CCH * HW + (size_t)c0 * HW;

#pragma unroll 4
    for (int c = 0; c < 128; c++) {
        size_t off = (size_t)c * HW;
        float fA = fp[off + n1];
        float fB = fp[off + n2];
        u64 v = 0ULL;
#pragma unroll
        for (int l = 0; l < LL; l++) v = fma2(ap[l], t3d[l][c], v);
        float lo, hi;
        upk2(lo, hi, v);
        op[off + n1] = fA + lo;
        op[off + n2] = fB + hi;
    }
}

extern "C" void kernel_launch(void* const* d_in, const int* in_sizes, int n_in,
                              void* d_out, int out_size) {
    const float* mask    = (const float*)d_in[0];
    const float* fea     = (const float*)d_in[1];
    const float* token_s = (const float*)d_in[2];
    const float* W1      = (const float*)d_in[3];
    const float* W2      = (const float*)d_in[4];
    const float* W3      = (const float*)d_in[5];
    const float* b3      = (const float*)d_in[6];
    float* out = (float*)d_out;

    wprep_kernel<<<64, 256>>>(W1, W2, W3);
    tokprep_kernel<<<dim3(BS, 10), 256>>>(token_s, b3);
    attn4_kernel<<<dim3(4, 128), 256>>>(mask, fea);
    out3_kernel<<<dim3(BS, 32, 2), 256>>>(fea, out);
}

// round 6
// speedup vs baseline: 1.3300x; 1.0509x over previous
#include <cuda_runtime.h>
#include <cstddef>

#define BS 8
#define CLS 4
#define CCH 256
#define HW 16384
#define LL 19
#define TK 256
#define MH 64
#define MW 64

typedef unsigned long long u64;

// Scratch (device globals: allocation is forbidden)
__device__ float g_M[TK * CCH];       // M[k][c] = sum_t W2[t][k] * W1[t][c]
__device__ float g_W3T[TK * CCH];     // W3T[k][c] = W3[c][k]
__device__ float g_U[BS][LL][TK];     // (tok @ M) / 16
__device__ float g_t3[BS][LL][CCH];   // tok @ W3^T + b3
__device__ float g_a[BS][HW][20];     // softmaxed attn weights (19 used, padded)

// ---------------- f32x2 packed helpers (sm_103a) ----------------
__device__ __forceinline__ u64 pk2(float lo, float hi) {
    u64 r;
    asm("mov.b64 %0, {%1, %2};" : "=l"(r) : "f"(lo), "f"(hi));
    return r;
}
__device__ __forceinline__ void upk2(float& lo, float& hi, u64 v) {
    asm("mov.b64 {%0, %1}, %2;" : "=f"(lo), "=f"(hi) : "l"(v));
}
__device__ __forceinline__ u64 fma2(u64 a, u64 b, u64 c) {
    u64 d;
    asm("fma.rn.f32x2 %0, %1, %2, %3;" : "=l"(d) : "l"(a), "l"(b), "l"(c));
    return d;
}

// ---------------------------------------------------------------------------
// wprep: M[k][c] = sum_t W2[t][k]*W1[t][c]  and  W3T[k][c] = W3[c][k]
// ---------------------------------------------------------------------------
__global__ void __launch_bounds__(256) wprep_kernel(const float* __restrict__ W1,
                                                    const float* __restrict__ W2,
                                                    const float* __restrict__ W3) {
    int k0 = blockIdx.x * 4;
    int c = threadIdx.x;
    __shared__ float w2s[256][4];
    __shared__ float w3s[256][5];
    for (int i = threadIdx.x; i < 1024; i += 256) {
        int r = i >> 2, j = i & 3;
        w2s[r][j] = W2[r * TK + k0 + j];
        w3s[r][j] = W3[r * TK + k0 + j];
    }
    __syncthreads();

    float acc[4] = {0.f, 0.f, 0.f, 0.f};
#pragma unroll 8
    for (int t = 0; t < 256; t++) {
        float w1 = W1[t * CCH + c];
#pragma unroll
        for (int j = 0; j < 4; j++) acc[j] = fmaf(w2s[t][j], w1, acc[j]);
    }
#pragma unroll
    for (int j = 0; j < 4; j++) {
        g_M[(k0 + j) * CCH + c] = acc[j];
        g_W3T[(k0 + j) * CCH + c] = w3s[c][j];
    }
}

// ---------------------------------------------------------------------------
// tokprep: U[b][l][c] = (1/16) sum_k tok[b][l][k]*M[k][c]
//          t3[b][l][c] = sum_k tok[b][l][k]*W3T[k][c] + b3[c]
// ---------------------------------------------------------------------------
__global__ void __launch_bounds__(256) tokprep_kernel(const float* __restrict__ token_s,
                                                      const float* __restrict__ b3) {
    int b = blockIdx.x;
    int y = blockIdx.y;
    int phase = y / 5;
    int l0 = (y % 5) * 4;
    int lcnt = (l0 + 4 <= LL) ? 4 : (LL - l0);
    int c = threadIdx.x;

    __shared__ float tok[4][256];
    for (int i = threadIdx.x; i < 4 * 256; i += 256) {
        int l = i >> 8, k = i & 255;
        tok[l][k] = (l < lcnt) ? token_s[(b * LL + l0 + l) * TK + k] : 0.f;
    }
    __syncthreads();

    const float* Mp = phase ? g_W3T : g_M;
    float acc[4] = {0.f, 0.f, 0.f, 0.f};
#pragma unroll 8
    for (int k = 0; k < 256; k++) {
        float m = Mp[k * CCH + c];
#pragma unroll
        for (int l = 0; l < 4; l++) acc[l] = fmaf(tok[l][k], m, acc[l]);
    }
    if (phase == 0) {
        for (int l = 0; l < lcnt; l++) g_U[b][l0 + l][c] = acc[l] * 0.0625f;
    } else {
        float bias = b3[c];
        for (int l = 0; l < lcnt; l++) g_t3[b][l0 + l][c] = acc[l] + bias;
    }
}

// ---------------------------------------------------------------------------
// attn5: smem-tiled, mask in registers, Phase B unroll 2.
// Block = (group g of 2 batches, image row of 128 px = 64 px-pairs).
// Phase A (thread = fixed pp, 8 ch): X[b][ch][pp] = sum_s m[b][s]*fea[src][ch][pp]
// Phase B (warp = (batch, 5 l), thread = 2 pp): acc += X * Udup
// Epilogue: softmax over 19 l per (b,px), zero where logit==0, store g_a.
// grid = (4, 128), 256 threads. smem = 43008 B.
// ---------------------------------------------------------------------------
__global__ void __launch_bounds__(256) attn5_kernel(const float* __restrict__ mask,
                                                    const float* __restrict__ fea) {
    __shared__ u64 Xs[2][32][64];     // 32 KB ; aliased as Asm at the end
    __shared__ u64 Udup[2][20][32];   // 10 KB

    int g = blockIdx.x;
    int row = blockIdx.y;
    int b0 = (g & 1) * 4 + (g >> 1);  // {0,2},{4,6},{1,3},{5,7}
    int b1 = b0 + 2;
    int p = g >> 1;                    // source parity: 0 -> fea 0..3, 1 -> 4..7
    int tid = threadIdx.x;
    int w = tid >> 5, lane = tid & 31;

    int pp = tid & 63;    // px-pair owned in Phase A (mask col mj == pp)
    int chb = tid >> 6;   // 0..3

    // mask values -> registers (duplicated pairs, *0.25)
    int mi = row >> 1;
    u64 mreg[2][4];
#pragma unroll
    for (int bi = 0; bi < 2; bi++) {
        int b = bi ? b1 : b0;
#pragma unroll
        for (int s = 0; s < 4; s++) {
            float m = 0.25f * __ldg(&mask[((b * CLS + s) * MH + mi) * MW + pp]);
            mreg[bi][s] = pk2(m, m);
        }
    }

    int bsel = w & 1;
    int l0 = (w >> 1) * 5;  // 0,5,10,15 (l=19 is a zero pad)

    const float* fbase[4];
#pragma unroll
    for (int s = 0; s < 4; s++)
        fbase[s] = fea + (size_t)(4 * p + s) * CCH * HW + row * 128 + 2 * pp;

    u64 acc[5][2];
#pragma unroll
    for (int i = 0; i < 5; i++) { acc[i][0] = 0ULL; acc[i][1] = 0ULL; }

    for (int kc = 0; kc < 8; kc++) {
        // build Udup for this chunk (row l=19 zero-padded)
        for (int idx = tid; idx < 2 * 20 * 32; idx += 256) {
            int bi = idx / 640;
            int rem = idx - bi * 640;
            int l = rem >> 5, k = rem & 31;
            float u = (l < LL) ? g_U[bi ? b1 : b0][l][kc * 32 + k] : 0.f;
            Udup[bi][l][k] = pk2(u, u);
        }
        // Phase A: thread covers 8 channels at its fixed pp
#pragma unroll
        for (int r = 0; r < 8; r++) {
            int ch = chb * 8 + r;
            size_t off = (size_t)(kc * 32 + ch) * HW;
            u64 f0 = *(const u64*)(fbase[0] + off);
            u64 f1 = *(const u64*)(fbase[1] + off);
            u64 f2 = *(const u64*)(fbase[2] + off);
            u64 f3 = *(const u64*)(fbase[3] + off);
            Xs[0][ch][pp] = fma2(mreg[0][3], f3,
                            fma2(mreg[0][2], f2,
                            fma2(mreg[0][1], f1,
                            fma2(mreg[0][0], f0, 0ULL))));
            Xs[1][ch][pp] = fma2(mreg[1][3], f3,
                            fma2(mreg[1][2], f2,
                            fma2(mreg[1][1], f1,
                            fma2(mreg[1][0], f0, 0ULL))));
        }
        __syncthreads();  // X + Udup ready

        const u64* Xb = &Xs[bsel][0][0];
        const u64* Ub = &Udup[bsel][0][0];
#pragma unroll 2
        for (int k = 0; k < 32; k++) {
            u64 x0 = Xb[k * 64 + lane];
            u64 x1 = Xb[k * 64 + lane + 32];
#pragma unroll
            for (int i = 0; i < 5; i++) {
                u64 u = Ub[(l0 + i) * 32 + k];
                acc[i][0] = fma2(x0, u, acc[i][0]);
                acc[i][1] = fma2(x1, u, acc[i][1]);
            }
        }
        __syncthreads();  // done reading before next chunk overwrites
    }

    // exchange logits via smem (alias Xs): Asm u64 view [2][20][64 pp]
    u64* Asm = &Xs[0][0][0];
#pragma unroll
    for (int i = 0; i < 5; i++) {
        Asm[(bsel * 20 + l0 + i) * 64 + lane] = acc[i][0];
        Asm[(bsel * 20 + l0 + i) * 64 + lane + 32] = acc[i][1];
    }
    __syncthreads();

    // softmax: thread = (bq, px)
    const float* Af = (const float*)Asm;  // [2][20][128]
    int bq = tid >> 7, px = tid & 127;
    int b = bq ? b1 : b0;
    float lg[LL];
#pragma unroll
    for (int l = 0; l < LL; l++) lg[l] = Af[(bq * 20 + l) * 128 + px];
    float mx = lg[0];
#pragma unroll
    for (int l = 1; l < LL; l++) mx = fmaxf(mx, lg[l]);
    float e[LL], sum = 0.f;
#pragma unroll
    for (int l = 0; l < LL; l++) { e[l] = __expf(lg[l] - mx); sum += e[l]; }
    float inv = 1.f / sum;
    float outv[20];
#pragma unroll
    for (int l = 0; l < LL; l++) outv[l] = (lg[l] != 0.f) ? e[l] * inv : 0.f;
    outv[19] = 0.f;
    float4* dst = (float4*)g_a[b][row * 128 + px];
#pragma unroll
    for (int q = 0; q < 5; q++) dst[q] = ((float4*)outv)[q];
}

// ---------------------------------------------------------------------------
// out4: out[b,c,n] = fea[b,c,n] + sum_l a[b,n,l] * t3[b,l,c]
// 4 adjacent px per thread (two f32x2 pairs) -> LDG.128/STG.128;
// t3 via broadcast LDS.64 amortized over 2 fma2.
// grid = (BS, 16 px-tiles of 1024, 2 c-halves of 128), 256 threads.
// ---------------------------------------------------------------------------
__global__ void __launch_bounds__(256) out4_kernel(const float* __restrict__ fea,
                                                   float* __restrict__ out) {
    int b = blockIdx.x;
    int c0 = blockIdx.z * 128;

    __shared__ u64 t3d[LL][128];  // duplicated pairs, 19456 B
    for (int idx = threadIdx.x; idx < LL * 128; idx += 256) {
        int l = idx >> 7, c = idx & 127;
        float v = g_t3[b][l][c0 + c];
        t3d[l][c] = pk2(v, v);
    }
    __syncthreads();

    int n0 = blockIdx.y * 1024 + threadIdx.x * 4;  // 4 adjacent pixels

    // pack a: ap1 = (a[n0], a[n0+1]), ap2 = (a[n0+2], a[n0+3]) per l
    u64 ap1[LL], ap2[LL];
    {
        const float4* pa0 = (const float4*)g_a[b][n0 + 0];
        const float4* pa1 = (const float4*)g_a[b][n0 + 1];
        const float4* pa2 = (const float4*)g_a[b][n0 + 2];
        const float4* pa3 = (const float4*)g_a[b][n0 + 3];
#pragma unroll
        for (int q = 0; q < 5; q++) {
            float4 qa = pa0[q], qb = pa1[q], qc = pa2[q], qd = pa3[q];
            int base = q * 4;
            if (base + 0 < LL) { ap1[base + 0] = pk2(qa.x, qb.x); ap2[base + 0] = pk2(qc.x, qd.x); }
            if (base + 1 < LL) { ap1[base + 1] = pk2(qa.y, qb.y); ap2[base + 1] = pk2(qc.y, qd.y); }
            if (base + 2 < LL) { ap1[base + 2] = pk2(qa.z, qb.z); ap2[base + 2] = pk2(qc.z, qd.z); }
            if (base + 3 < LL) { ap1[base + 3] = pk2(qa.w, qb.w); ap2[base + 3] = pk2(qc.w, qd.w); }
        }
    }

    const float* fp = fea + (size_t)b * CCH * HW + (size_t)c0 * HW + n0;
    float* op = out + (size_t)b * CCH * HW + (size_t)c0 * HW + n0;

#pragma unroll 4
    for (int c = 0; c < 128; c++) {
        size_t off = (size_t)c * HW;
        ulonglong2 fv = *(const ulonglong2*)(fp + off);  // LDG.128: 4 px
        u64 v1 = fv.x, v2 = fv.y;
#pragma unroll
        for (int l = 0; l < LL; l++) {
            u64 t = t3d[l][c];
            v1 = fma2(ap1[l], t, v1);
            v2 = fma2(ap2[l], t, v2);
        }
        ulonglong2 ov;
        ov.x = v1;
        ov.y = v2;
        *(ulonglong2*)(op + off) = ov;  // STG.128
    }
}

extern "C" void kernel_launch(void* const* d_in, const int* in_sizes, int n_in,
                              void* d_out, int out_size) {
    const float* mask    = (const float*)d_in[0];
    const float* fea     = (const float*)d_in[1];
    const float* token_s = (const float*)d_in[2];
    const float* W1      = (const float*)d_in[3];
    const float* W2      = (const float*)d_in[4];
    const float* W3      = (const float*)d_in[5];
    const float* b3      = (const float*)d_in[6];
    float* out = (float*)d_out;

    wprep_kernel<<<64, 256>>>(W1, W2, W3);
    tokprep_kernel<<<dim3(BS, 10), 256>>>(token_s, b3);
    attn5_kernel<<<dim3(4, 128), 256>>>(mask, fea);
    out4_kernel<<<dim3(BS, 16, 2), 256>>>(fea, out);
}

// round 9
// speedup vs baseline: 1.5805x; 1.1884x over previous
#include <cuda_runtime.h>
#include <cstddef>

#define BS 8
#define CLS 4
#define CCH 256
#define HW 16384
#define LL 19
#define TK 256
#define MH 64
#define MW 64

typedef unsigned long long u64;

// Scratch (device globals: allocation is forbidden)
__device__ float g_M[TK * CCH];       // M[k][c] = sum_t W2[t][k] * W1[t][c]
__device__ float g_W3T[TK * CCH];     // W3T[k][c] = W3[c][k]
__device__ float g_U[BS][LL][TK];     // (tok @ M) / 16
__device__ float g_t3[BS][LL][CCH];   // tok @ W3^T + b3
__device__ float g_a[BS][HW][20];     // softmaxed attn weights (19 used, padded)

// ---------------- f32x2 packed helpers (sm_103a) ----------------
__device__ __forceinline__ u64 pk2(float lo, float hi) {
    u64 r;
    asm("mov.b64 %0, {%1, %2};" : "=l"(r) : "f"(lo), "f"(hi));
    return r;
}
__device__ __forceinline__ void upk2(float& lo, float& hi, u64 v) {
    asm("mov.b64 {%0, %1}, %2;" : "=f"(lo), "=f"(hi) : "l"(v));
}
__device__ __forceinline__ u64 fma2(u64 a, u64 b, u64 c) {
    u64 d;
    asm("fma.rn.f32x2 %0, %1, %2, %3;" : "=l"(d) : "l"(a), "l"(b), "l"(c));
    return d;
}

// ---------------------------------------------------------------------------
// wprep: M[k][c] = sum_t W2[t][k]*W1[t][c]  and  W3T[k][c] = W3[c][k]
// ---------------------------------------------------------------------------
__global__ void __launch_bounds__(256) wprep_kernel(const float* __restrict__ W1,
                                                    const float* __restrict__ W2,
                                                    const float* __restrict__ W3) {
    int k0 = blockIdx.x * 4;
    int c = threadIdx.x;
    __shared__ float w2s[256][4];
    __shared__ float w3s[256][5];
    for (int i = threadIdx.x; i < 1024; i += 256) {
        int r = i >> 2, j = i & 3;
        w2s[r][j] = W2[r * TK + k0 + j];
        w3s[r][j] = W3[r * TK + k0 + j];
    }
    __syncthreads();

    float acc[4] = {0.f, 0.f, 0.f, 0.f};
#pragma unroll 8
    for (int t = 0; t < 256; t++) {
        float w1 = W1[t * CCH + c];
#pragma unroll
        for (int j = 0; j < 4; j++) acc[j] = fmaf(w2s[t][j], w1, acc[j]);
    }
#pragma unroll
    for (int j = 0; j < 4; j++) {
        g_M[(k0 + j) * CCH + c] = acc[j];
        g_W3T[(k0 + j) * CCH + c] = w3s[c][j];
    }
}

// ---------------------------------------------------------------------------
// tokprep: U[b][l][c] = (1/16) sum_k tok[b][l][k]*M[k][c]
//          t3[b][l][c] = sum_k tok[b][l][k]*W3T[k][c] + b3[c]
// ---------------------------------------------------------------------------
__global__ void __launch_bounds__(256) tokprep_kernel(const float* __restrict__ token_s,
                                                      const float* __restrict__ b3) {
    int b = blockIdx.x;
    int y = blockIdx.y;
    int phase = y / 5;
    int l0 = (y % 5) * 4;
    int lcnt = (l0 + 4 <= LL) ? 4 : (LL - l0);
    int c = threadIdx.x;

    __shared__ float tok[4][256];
    for (int i = threadIdx.x; i < 4 * 256; i += 256) {
        int l = i >> 8, k = i & 255;
        tok[l][k] = (l < lcnt) ? token_s[(b * LL + l0 + l) * TK + k] : 0.f;
    }
    __syncthreads();

    const float* Mp = phase ? g_W3T : g_M;
    float acc[4] = {0.f, 0.f, 0.f, 0.f};
#pragma unroll 8
    for (int k = 0; k < 256; k++) {
        float m = Mp[k * CCH + c];
#pragma unroll
        for (int l = 0; l < 4; l++) acc[l] = fmaf(tok[l][k], m, acc[l]);
    }
    if (phase == 0) {
        for (int l = 0; l < lcnt; l++) g_U[b][l0 + l][c] = acc[l] * 0.0625f;
    } else {
        float bias = b3[c];
        for (int l = 0; l < lcnt; l++) g_t3[b][l0 + l][c] = acc[l] + bias;
    }
}

// ---------------------------------------------------------------------------
// attn6: software-pipelined smem-tiled GEMM. 16-ch chunks, 16 chunks.
// Prefetch chunk k+1 (fea -> 16 u64 regs, U -> float4) during Phase B of k,
// so no warp ever stalls on a global load at the STS site.
// Block = (group g of 2 batches, image row of 128 px = 64 px-pairs).
// grid = (4, 128), 256 threads. smem = 25.6 KB.
// ---------------------------------------------------------------------------
__global__ void __launch_bounds__(256) attn6_kernel(const float* __restrict__ mask,
                                                    const float* __restrict__ fea) {
    __shared__ u64 Xs[2][20][64];     // 20480 B; rows 0..15 = X, aliased as logits at end
    __shared__ u64 Udup[2][20][16];   // 5120 B

    int g = blockIdx.x;
    int row = blockIdx.y;
    int b0 = (g & 1) * 4 + (g >> 1);  // {0,2},{4,6},{1,3},{5,7}
    int b1 = b0 + 2;
    int p = g >> 1;                    // src parity: 0 -> fea 0..3, 1 -> fea 4..7
    int tid = threadIdx.x;
    int w = tid >> 5, lane = tid & 31;

    int pp = tid & 63;    // px-pair owned in Phase A
    int chb = tid >> 6;   // 0..3 -> 4 channels each per 16-ch chunk

    // mask values -> registers (duplicated pairs, *0.25)
    int mi = row >> 1;
    u64 mreg[2][4];
#pragma unroll
    for (int bi = 0; bi < 2; bi++) {
        int b = bi ? b1 : b0;
#pragma unroll
        for (int s = 0; s < 4; s++) {
            float m = 0.25f * __ldg(&mask[((b * CLS + s) * MH + mi) * MW + pp]);
            mreg[bi][s] = pk2(m, m);
        }
    }

    int bsel = w & 1;
    int l0 = (w >> 1) * 5;  // 0,5,10,15 (l=19 is a zero pad)

    const float* fbase[4];
#pragma unroll
    for (int s = 0; s < 4; s++)
        fbase[s] = fea + (size_t)(4 * p + s) * CCH * HW + row * 128 + 2 * pp;

    // U prefetch job for threads < 160: (bi, l, k4)
    int uj_bi = tid / 80;
    int uj_rem = tid % 80;
    int uj_l = uj_rem >> 2;
    int uj_k4 = uj_rem & 3;
    const float* uj_src = (tid < 160 && uj_l < LL)
        ? &g_U[uj_bi ? b1 : b0][uj_l][uj_k4 * 4] : 0;

    u64 f[4][4];     // prefetched fea: [r][src]
    float4 uq;       // prefetched U quad

    // ---- prefetch chunk 0 ----
#pragma unroll
    for (int r = 0; r < 4; r++) {
        size_t off = (size_t)(chb * 4 + r) * HW;
#pragma unroll
        for (int s = 0; s < 4; s++) f[r][s] = *(const u64*)(fbase[s] + off);
    }
    uq = make_float4(0.f, 0.f, 0.f, 0.f);
    if (uj_src) uq = *(const float4*)uj_src;

    u64 acc[5][2];
#pragma unroll
    for (int i = 0; i < 5; i++) { acc[i][0] = 0ULL; acc[i][1] = 0ULL; }

    for (int kc = 0; kc < 16; kc++) {
        // ---- store phase: combine prefetched fea -> X; U -> Udup ----
#pragma unroll
        for (int r = 0; r < 4; r++) {
            int ch = chb * 4 + r;
            Xs[0][ch][pp] = fma2(mreg[0][3], f[r][3],
                            fma2(mreg[0][2], f[r][2],
                            fma2(mreg[0][1], f[r][1],
                            fma2(mreg[0][0], f[r][0], 0ULL))));
            Xs[1][ch][pp] = fma2(mreg[1][3], f[r][3],
                            fma2(mreg[1][2], f[r][2],
                            fma2(mreg[1][1], f[r][1],
                            fma2(mreg[1][0], f[r][0], 0ULL))));
        }
        if (tid < 160) {
            Udup[uj_bi][uj_l][uj_k4 * 4 + 0] = pk2(uq.x, uq.x);
            Udup[uj_bi][uj_l][uj_k4 * 4 + 1] = pk2(uq.y, uq.y);
            Udup[uj_bi][uj_l][uj_k4 * 4 + 2] = pk2(uq.z, uq.z);
            Udup[uj_bi][uj_l][uj_k4 * 4 + 3] = pk2(uq.w, uq.w);
        }
        __syncthreads();

        // ---- issue prefetch for chunk kc+1 (overlaps Phase B below) ----
        if (kc < 15) {
#pragma unroll
            for (int r = 0; r < 4; r++) {
                size_t off = (size_t)((kc + 1) * 16 + chb * 4 + r) * HW;
#pragma unroll
                for (int s = 0; s < 4; s++) f[r][s] = *(const u64*)(fbase[s] + off);
            }
            if (uj_src) uq = *(const float4*)(uj_src + (kc + 1) * 16);
        }

        // ---- Phase B: acc += X * Udup ----
        const u64* Xb = &Xs[bsel][0][0];
        const u64* Ub = &Udup[bsel][0][0];
#pragma unroll 4
        for (int k = 0; k < 16; k++) {
            u64 x0 = Xb[k * 64 + lane];
            u64 x1 = Xb[k * 64 + lane + 32];
#pragma unroll
            for (int i = 0; i < 5; i++) {
                u64 u = Ub[(l0 + i) * 16 + k];
                acc[i][0] = fma2(x0, u, acc[i][0]);
                acc[i][1] = fma2(x1, u, acc[i][1]);
            }
        }
        __syncthreads();
    }

    // exchange logits via smem (alias Xs): [2][20][64 pp]
    u64* Asm = &Xs[0][0][0];
#pragma unroll
    for (int i = 0; i < 5; i++) {
        Asm[(bsel * 20 + l0 + i) * 64 + lane] = acc[i][0];
        Asm[(bsel * 20 + l0 + i) * 64 + lane + 32] = acc[i][1];
    }
    __syncthreads();

    // softmax: thread = (bq, px)
    const float* Af = (const float*)Asm;  // [2][20][128]
    int bq = tid >> 7, px = tid & 127;
    int b = bq ? b1 : b0;
    float lg[LL];
#pragma unroll
    for (int l = 0; l < LL; l++) lg[l] = Af[(bq * 20 + l) * 128 + px];
    float mx = lg[0];
#pragma unroll
    for (int l = 1; l < LL; l++) mx = fmaxf(mx, lg[l]);
    float e[LL], sum = 0.f;
#pragma unroll
    for (int l = 0; l < LL; l++) { e[l] = __expf(lg[l] - mx); sum += e[l]; }
    float inv = 1.f / sum;
    float outv[20];
#pragma unroll
    for (int l = 0; l < LL; l++) outv[l] = (lg[l] != 0.f) ? e[l] * inv : 0.f;
    outv[19] = 0.f;
    float4* dst = (float4*)g_a[b][row * 128 + px];
#pragma unroll
    for (int q = 0; q < 5; q++) dst[q] = ((float4*)outv)[q];
}

// ---------------------------------------------------------------------------
// out5: out[b,c,n] = fea[b,c,n] + sum_l a[b,n,l] * t3[b,l,c]
// 2 ADJACENT px per thread (one f32x2): a packed in 19 u64, t3 via
// broadcast LDS.128 (2 channels per access). LDG.64/STG.64 coalesced.
// grid = (BS, 64 px-tiles of 256, 2 c-halves of 128), 128 threads.
// ---------------------------------------------------------------------------
__global__ void __launch_bounds__(128) out5_kernel(const float* __restrict__ fea,
                                                   float* __restrict__ out) {
    int b = blockIdx.x;
    int c0 = blockIdx.z * 128;

    __shared__ u64 t3d[LL][128];  // duplicated pairs, 19456 B
    for (int idx = threadIdx.x; idx < LL * 128; idx += 128) {
        int l = idx >> 7, c = idx & 127;
        float v = g_t3[b][l][c0 + c];
        t3d[l][c] = pk2(v, v);
    }
    __syncthreads();

    int n0 = blockIdx.y * 256 + threadIdx.x * 2;  // 2 adjacent pixels

    // pack a: ap[l] = (a[n0][l], a[n0+1][l])
    u64 ap[LL];
    {
        const float4* pa0 = (const float4*)g_a[b][n0 + 0];
        const float4* pa1 = (const float4*)g_a[b][n0 + 1];
#pragma unroll
        for (int q = 0; q < 5; q++) {
            float4 qa = pa0[q], qb = pa1[q];
            int base = q * 4;
            if (base + 0 < LL) ap[base + 0] = pk2(qa.x, qb.x);
            if (base + 1 < LL) ap[base + 1] = pk2(qa.y, qb.y);
            if (base + 2 < LL) ap[base + 2] = pk2(qa.z, qb.z);
            if (base + 3 < LL) ap[base + 3] = pk2(qa.w, qb.w);
        }
    }

    const float* fp = fea + (size_t)b * CCH * HW + (size_t)c0 * HW + n0;
    float* op = out + (size_t)b * CCH * HW + (size_t)c0 * HW + n0;

#pragma unroll 4
    for (int c = 0; c < 128; c += 2) {
        size_t offA = (size_t)c * HW;
        size_t offB = offA + HW;
        u64 vA = *(const u64*)(fp + offA);  // init with fea (saves final add)
        u64 vB = *(const u64*)(fp + offB);
#pragma unroll
        for (int l = 0; l < LL; l++) {
            ulonglong2 t = *(const ulonglong2*)&t3d[l][c];  // LDS.128 broadcast
            vA = fma2(ap[l], t.x, vA);
            vB = fma2(ap[l], t.y, vB);
        }
        *(u64*)(op + offA) = vA;
        *(u64*)(op + offB) = vB;
    }
}

extern "C" void kernel_launch(void* const* d_in, const int* in_sizes, int n_in,
                              void* d_out, int out_size) {
    const float* mask    = (const float*)d_in[0];
    const float* fea     = (const float*)d_in[1];
    const float* token_s = (const float*)d_in[2];
    const float* W1      = (const float*)d_in[3];
    const float* W2      = (const float*)d_in[4];
    const float* W3      = (const float*)d_in[5];
    const float* b3      = (const float*)d_in[6];
    float* out = (float*)d_out;

    wprep_kernel<<<64, 256>>>(W1, W2, W3);
    tokprep_kernel<<<dim3(BS, 10), 256>>>(token_s, b3);
    attn6_kernel<<<dim3(4, 128), 256>>>(mask, fea);
    out5_kernel<<<dim3(BS, 64, 2), 128>>>(fea, out);
}